// round 3
// baseline (speedup 1.0000x reference)
#include <cuda_runtime.h>

// Problem constants (fixed by the reference)
#define NATOMS  50000
#define EMB     256
#define PIN     64
#define POUT    64
#define NRBF    16
#define KMAXN   32
#define NEDGES  1600000

// Scratch (device globals — no allocation allowed)
__device__ float g_xb[NATOMS * PIN];                       // silu(h @ W_down)   12.8 MB
__device__ int   g_win[NATOMS * KMAXN];                    // winning edge id     6.4 MB
__device__ float g_xba2[(size_t)NATOMS * NRBF * PIN];      // einsum result     204.8 MB
__device__ float g_h2[NATOMS * POUT];                      // bilinear result    12.8 MB

__device__ __forceinline__ float silu_f(float x) {
    return x / (1.0f + __expf(-x));
}

// ---------------------------------------------------------------------------
// Phase A: deterministic "last update wins" scatter — record max edge id per
// (dst_atom, neighbor_slot). Matches XLA's sequential scatter-set semantics.
// es/ts = word stride per logical element (1 = int32, 2 = int64 low word).
// ---------------------------------------------------------------------------
__global__ void init_win_kernel() {
    int i = blockIdx.x * blockDim.x + threadIdx.x;
    if (i < NATOMS * KMAXN) g_win[i] = -1;
}

__global__ void scatter_win_kernel(const int* __restrict__ ei,
                                   const int* __restrict__ tni,
                                   int es, int ts)
{
    int e = blockIdx.x * blockDim.x + threadIdx.x;
    if (e >= NEDGES) return;
    int dst = ei[(size_t)(NEDGES + e) * es];   // edge_index[1][e]
    int k   = tni[(size_t)e * ts];             // target_neighbor_idx[e]
    if ((unsigned)dst < NATOMS && (unsigned)k < KMAXN)
        atomicMax(&g_win[dst * KMAXN + k], e);
}

// ---------------------------------------------------------------------------
// Register-tiled fp32 GEMM core (device inline): C[M,N] = op(A[M,K] @ B[K,N])
// ---------------------------------------------------------------------------
template<int BM, int BN, int BK, int TM, int TN, bool SILU, bool SCALE>
__device__ __forceinline__
void gemm_core(const float* __restrict__ A, const float* __restrict__ B,
               float* __restrict__ C, int M, int N, int K,
               const float* __restrict__ scale_p)
{
    constexpr int THREADS = (BM/TM)*(BN/TN);
    __shared__ __align__(16) float As[BK][BM + 1];   // k-major for conflict-free reads
    __shared__ __align__(16) float Bs[BK][BN];

    const int t  = threadIdx.x;
    const int m0 = blockIdx.y * BM;
    const int n0 = blockIdx.x * BN;
    const int trow = (t / (BN/TN)) * TM;
    const int tcol = (t % (BN/TN)) * TN;

    float acc[TM][TN];
#pragma unroll
    for (int i = 0; i < TM; i++)
#pragma unroll
        for (int j = 0; j < TN; j++) acc[i][j] = 0.0f;

    for (int k0 = 0; k0 < K; k0 += BK) {
#pragma unroll
        for (int i = t; i < BM * BK; i += THREADS) {
            int m = i / BK, k = i % BK;
            float v = (m0 + m < M) ? A[(size_t)(m0 + m) * K + k0 + k] : 0.0f;
            As[k][m] = v;
        }
#pragma unroll
        for (int i = t; i < BK * BN; i += THREADS) {
            int k = i / BN, n = i % BN;
            Bs[k][n] = B[(size_t)(k0 + k) * N + n0 + n];
        }
        __syncthreads();

#pragma unroll
        for (int k = 0; k < BK; k++) {
            float af[TM], bf[TN];
#pragma unroll
            for (int i = 0; i < TM; i++) af[i] = As[k][trow + i];
#pragma unroll
            for (int j = 0; j < TN; j++) bf[j] = Bs[k][tcol + j];
#pragma unroll
            for (int i = 0; i < TM; i++)
#pragma unroll
                for (int j = 0; j < TN; j++) acc[i][j] = fmaf(af[i], bf[j], acc[i][j]);
        }
        __syncthreads();
    }

    const float s = SCALE ? *scale_p : 1.0f;
#pragma unroll
    for (int i = 0; i < TM; i++) {
        int m = m0 + trow + i;
        if (m >= M) continue;
#pragma unroll
        for (int j = 0; j < TN; j++) {
            float v = acc[i][j] * s;
            if (SILU) v = silu_f(v);
            C[(size_t)m * N + n0 + tcol + j] = v;
        }
    }
}

// GEMM1: g_xb = silu(h @ W_down)      [50000,256] x [256,64]
__global__ __launch_bounds__(256)
void gemm1_kernel(const float* __restrict__ h, const float* __restrict__ W_down) {
    gemm_core<128, 64, 16, 8, 4, true, false>(h, W_down, g_xb, NATOMS, PIN, EMB, nullptr);
}

// GEMM2: g_h2 = (g_xba2 @ W_bilinear) * scale   [50000,1024] x [1024,64]
__global__ __launch_bounds__(256)
void gemm2_kernel(const float* __restrict__ W_bil, const float* __restrict__ scale) {
    gemm_core<128, 64, 16, 8, 4, false, true>(g_xba2, W_bil, g_h2, NATOMS, POUT, NRBF * PIN, scale);
}

// GEMM3: out = silu(g_h2 @ W_up)      [50000,64] x [64,256]
__global__ __launch_bounds__(256)
void gemm3_kernel(const float* __restrict__ W_up, float* __restrict__ out) {
    gemm_core<128, 64, 16, 8, 4, true, false>(g_h2, W_up, out, NATOMS, EMB, POUT, nullptr);
}

// ---------------------------------------------------------------------------
// Fused gather + rbf einsum: one warp per atom.
//   xs[k][:]  = g_xb[src(win[atom,k])]  (0 if empty slot)
//   g_xba2[atom,r,d] = sum_k rb[atom,r,k] * xs[k][d]
// ---------------------------------------------------------------------------
__global__ __launch_bounds__(128)
void einsum_kernel(const float* __restrict__ rad, const int* __restrict__ ei, int es)
{
    const int warp = threadIdx.x >> 5;
    const int lane = threadIdx.x & 31;
    const int atom = blockIdx.x * 4 + warp;   // grid = 12500, exact

    __shared__ __align__(16) float xs_all[4][KMAXN * PIN];     // 4 x 8 KB
    __shared__ __align__(16) float rbs_all[4][NRBF * KMAXN];   // 4 x 2 KB
    __shared__ int srcs_all[4][KMAXN];

    float* xs   = xs_all[warp];
    float* rbs  = rbs_all[warp];
    int*   srcs = srcs_all[warp];

    // winning source atom per neighbor slot
    {
        int e = g_win[atom * KMAXN + lane];
        int src = -1;
        if (e >= 0) {
            src = ei[(size_t)e * es];   // edge_index[0][e]
            if ((unsigned)src >= NATOMS) src = -1;
        }
        srcs[lane] = src;
    }
    __syncwarp();

    // stage rad_basis[atom] : 512 floats = 128 float4
    {
        const float4* rg = reinterpret_cast<const float4*>(rad + (size_t)atom * NRBF * KMAXN);
        float4* rs4 = reinterpret_cast<float4*>(rbs);
#pragma unroll
        for (int i = 0; i < 4; i++) rs4[lane + 32 * i] = rg[lane + 32 * i];
    }

    // stage x rows: 2 slots per pass, 64B per row (L2-resident table)
#pragma unroll
    for (int kk = 0; kk < KMAXN; kk += 2) {
        int k = kk + (lane >> 4);
        int f = lane & 15;
        int src = srcs[k];
        float4 v = make_float4(0.f, 0.f, 0.f, 0.f);
        if (src >= 0) v = reinterpret_cast<const float4*>(g_xb + (size_t)src * PIN)[f];
        reinterpret_cast<float4*>(xs + k * PIN)[f] = v;
    }
    __syncwarp();

    // rank-1 accumulation: lane owns 4 r's x 8 d's
    const int rg_ = lane >> 3;   // 0..3
    const int dg  = lane & 7;    // 0..7
    float acc[4][8];
#pragma unroll
    for (int a = 0; a < 4; a++)
#pragma unroll
        for (int b = 0; b < 8; b++) acc[a][b] = 0.0f;

#pragma unroll
    for (int k = 0; k < KMAXN; k++) {
        float4 xv0 = *reinterpret_cast<const float4*>(xs + k * PIN + dg * 8);
        float4 xv1 = *reinterpret_cast<const float4*>(xs + k * PIN + dg * 8 + 4);
#pragma unroll
        for (int rr = 0; rr < 4; rr++) {
            float w = rbs[(rg_ * 4 + rr) * KMAXN + k];
            acc[rr][0] = fmaf(w, xv0.x, acc[rr][0]);
            acc[rr][1] = fmaf(w, xv0.y, acc[rr][1]);
            acc[rr][2] = fmaf(w, xv0.z, acc[rr][2]);
            acc[rr][3] = fmaf(w, xv0.w, acc[rr][3]);
            acc[rr][4] = fmaf(w, xv1.x, acc[rr][4]);
            acc[rr][5] = fmaf(w, xv1.y, acc[rr][5]);
            acc[rr][6] = fmaf(w, xv1.z, acc[rr][6]);
            acc[rr][7] = fmaf(w, xv1.w, acc[rr][7]);
        }
    }

    // write [atom][r][d] (flat index r*64+d matches W_bilinear row order)
    float* outp = g_xba2 + (size_t)atom * NRBF * PIN;
#pragma unroll
    for (int rr = 0; rr < 4; rr++) {
        int r = rg_ * 4 + rr;
        float4 o0 = make_float4(acc[rr][0], acc[rr][1], acc[rr][2], acc[rr][3]);
        float4 o1 = make_float4(acc[rr][4], acc[rr][5], acc[rr][6], acc[rr][7]);
        reinterpret_cast<float4*>(outp + r * PIN + dg * 8)[0] = o0;
        reinterpret_cast<float4*>(outp + r * PIN + dg * 8 + 4)[0] = o1;
    }
}

// ---------------------------------------------------------------------------
// Launch — kernel launches ONLY (graph-capturable, no other runtime APIs)
// ---------------------------------------------------------------------------
extern "C" void kernel_launch(void* const* d_in, const int* in_sizes, int n_in,
                              void* d_out, int out_size)
{
    const float* h         = (const float*)d_in[0];   // [50000,256]
    const float* rad_basis = (const float*)d_in[1];   // [50000,16,32]
    const int*   edge_idx  = (const int*)d_in[2];     // [2,1.6M] int32 OR int64
    const int*   tni       = (const int*)d_in[3];     // [1.6M]   int32 OR int64
    const float* W_down    = (const float*)d_in[4];   // [256,64]
    const float* W_bil     = (const float*)d_in[5];   // [1024,64]
    const float* W_up      = (const float*)d_in[6];   // [64,256]
    const float* scale     = (const float*)d_in[7];   // [1]
    float* out = (float*)d_out;                       // [50000,256]

    // Word stride per logical index element: 1 if harness passed int32,
    // 2 if it passed raw int64 (little-endian low word holds the value).
    // in_sizes is the element count per the declared metadata dtype; if the
    // dtype stayed int64 the harness may report logical elements, so fall
    // back to detecting 2x-sized buffers.
    int es = (in_sizes[2] >= 2 * NEDGES * 2) ? 2 : 1;
    int ts = (in_sizes[3] >= NEDGES * 2) ? 2 : 1;

    init_win_kernel<<<(NATOMS * KMAXN + 255) / 256, 256>>>();
    scatter_win_kernel<<<(NEDGES + 255) / 256, 256>>>(edge_idx, tni, es, ts);

    { dim3 grid(1, (NATOMS + 127) / 128);
      gemm1_kernel<<<grid, 256>>>(h, W_down); }

    einsum_kernel<<<NATOMS / 4, 128>>>(rad_basis, edge_idx, es);

    { dim3 grid(1, (NATOMS + 127) / 128);
      gemm2_kernel<<<grid, 256>>>(W_bil, scale); }

    { dim3 grid(EMB / 64, (NATOMS + 127) / 128);
      gemm3_kernel<<<grid, 256>>>(W_up, out); }
}

// round 4
// speedup vs baseline: 1.7451x; 1.7451x over previous
#include <cuda_runtime.h>
#include <mma.h>

using namespace nvcuda;

// Problem constants (fixed by the reference)
#define NATOMS  50000
#define EMB     256
#define PIN     64
#define POUT    64
#define NRBF    16
#define KMAXN   32
#define NEDGES  1600000
#define NPAD    50048          // 391 * 128 (padded row count for tile-exact GEMMs)

// Scratch (device globals — no allocation allowed; zero-initialized at load,
// padded rows are never written and stay zero)
__device__ float g_xb[NPAD * PIN];                      // silu(h @ W_down)
__device__ int   g_win[NATOMS * KMAXN];                 // winning edge id
__device__ float g_xba2[(size_t)NPAD * NRBF * PIN];     // einsum result
__device__ float g_h2[NPAD * POUT];                     // bilinear result

__device__ __forceinline__ float silu_f(float x) {
    return x / (1.0f + __expf(-x));
}

// ---------------------------------------------------------------------------
// Phase A: deterministic "last update wins" scatter (matches XLA .at[].set)
// ---------------------------------------------------------------------------
__global__ void init_win_kernel() {
    int i = blockIdx.x * blockDim.x + threadIdx.x;
    if (i < NATOMS * KMAXN) g_win[i] = -1;
}

__global__ void scatter_win_kernel(const int* __restrict__ ei,
                                   const int* __restrict__ tni,
                                   int es, int ts)
{
    int e = blockIdx.x * blockDim.x + threadIdx.x;
    if (e >= NEDGES) return;
    int dst = ei[(size_t)(NEDGES + e) * es];   // edge_index[1][e]
    int k   = tni[(size_t)e * ts];             // target_neighbor_idx[e]
    if ((unsigned)dst < NATOMS && (unsigned)k < KMAXN)
        atomicMax(&g_win[dst * KMAXN + k], e);
}

// ---------------------------------------------------------------------------
// tf32 wmma GEMM core: C[BM=128, BN=64 tile] = op(A @ B), fp32 accumulate.
// 256 threads = 8 warps in 4(M) x 2(N); warp tile 32x32 = 2x2 m16n16k8 frags.
// ---------------------------------------------------------------------------
template<bool SILU, bool SCALE>
__device__ __forceinline__
void wgemm_core(const float* __restrict__ A, const float* __restrict__ B,
                float* __restrict__ C, int Mload, int Mstore,
                int ldb, int ldc, int K, const float* __restrict__ scale_p)
{
    constexpr int BM = 128, BN = 64, BK = 32;
    constexpr int LDA = BK + 4;   // 36
    constexpr int LDB = BN + 4;   // 68

    __shared__ __align__(16) float sraw[BM * LDB];      // 8704 floats = 34.8 KB
    float* As = sraw;                                    // [128][36] = 4608
    float* Bs = sraw + BM * LDA;                         // [32][68]  = 2176
    float* Cs = sraw;                                    // aliases after compute

    const int t  = threadIdx.x;
    const int m0 = blockIdx.y * BM;
    const int n0 = blockIdx.x * BN;
    const int warp = t >> 5;
    const int wm = (warp >> 1) * 32;
    const int wn = (warp & 1) * 32;

    wmma::fragment<wmma::accumulator, 16, 16, 8, float> c[2][2];
#pragma unroll
    for (int i = 0; i < 2; i++)
#pragma unroll
        for (int j = 0; j < 2; j++) wmma::fill_fragment(c[i][j], 0.0f);

    for (int k0 = 0; k0 < K; k0 += BK) {
        // A tile: 128x32, 4 float4 per thread
#pragma unroll
        for (int i = 0; i < 4; i++) {
            int row = (t >> 3) + i * 32;
            int col = (t & 7) * 4;
            float4 v = make_float4(0.f, 0.f, 0.f, 0.f);
            int gm = m0 + row;
            if (gm < Mload)
                v = *reinterpret_cast<const float4*>(A + (size_t)gm * K + k0 + col);
            v.x = wmma::__float_to_tf32(v.x);
            v.y = wmma::__float_to_tf32(v.y);
            v.z = wmma::__float_to_tf32(v.z);
            v.w = wmma::__float_to_tf32(v.w);
            *reinterpret_cast<float4*>(As + row * LDA + col) = v;
        }
        // B tile: 32x64, 2 float4 per thread
#pragma unroll
        for (int i = 0; i < 2; i++) {
            int row = (t >> 4) + i * 16;
            int col = (t & 15) * 4;
            float4 v = *reinterpret_cast<const float4*>(B + (size_t)(k0 + row) * ldb + n0 + col);
            v.x = wmma::__float_to_tf32(v.x);
            v.y = wmma::__float_to_tf32(v.y);
            v.z = wmma::__float_to_tf32(v.z);
            v.w = wmma::__float_to_tf32(v.w);
            *reinterpret_cast<float4*>(Bs + row * LDB + col) = v;
        }
        __syncthreads();

#pragma unroll
        for (int kk = 0; kk < BK; kk += 8) {
            wmma::fragment<wmma::matrix_a, 16, 16, 8, wmma::precision::tf32, wmma::row_major> a[2];
            wmma::fragment<wmma::matrix_b, 16, 16, 8, wmma::precision::tf32, wmma::row_major> b[2];
#pragma unroll
            for (int i = 0; i < 2; i++)
                wmma::load_matrix_sync(a[i], As + (wm + i * 16) * LDA + kk, LDA);
#pragma unroll
            for (int j = 0; j < 2; j++)
                wmma::load_matrix_sync(b[j], Bs + kk * LDB + wn + j * 16, LDB);
#pragma unroll
            for (int i = 0; i < 2; i++)
#pragma unroll
                for (int j = 0; j < 2; j++)
                    wmma::mma_sync(c[i][j], a[i], b[j], c[i][j]);
        }
        __syncthreads();
    }

    // epilogue: scale / silu on accumulator elements
    const float s = SCALE ? *scale_p : 1.0f;
#pragma unroll
    for (int i = 0; i < 2; i++)
#pragma unroll
        for (int j = 0; j < 2; j++)
#pragma unroll
            for (int e = 0; e < c[i][j].num_elements; e++) {
                float v = c[i][j].x[e] * s;
                if (SILU) v = silu_f(v);
                c[i][j].x[e] = v;
            }

    if (m0 + BM <= Mstore) {
        // full tile: direct stores
#pragma unroll
        for (int i = 0; i < 2; i++)
#pragma unroll
            for (int j = 0; j < 2; j++)
                wmma::store_matrix_sync(C + (size_t)(m0 + wm + i * 16) * ldc + n0 + wn + j * 16,
                                        c[i][j], ldc, wmma::mem_row_major);
    } else {
        // tail tile: stage in smem, guarded copy
#pragma unroll
        for (int i = 0; i < 2; i++)
#pragma unroll
            for (int j = 0; j < 2; j++)
                wmma::store_matrix_sync(Cs + (wm + i * 16) * LDB + wn + j * 16,
                                        c[i][j], LDB, wmma::mem_row_major);
        __syncthreads();
        for (int idx = t; idx < BM * BN; idx += 256) {
            int r = idx >> 6, cc = idx & 63;
            if (m0 + r < Mstore)
                C[(size_t)(m0 + r) * ldc + n0 + cc] = Cs[r * LDB + cc];
        }
    }
}

// GEMM1: g_xb = silu(h @ W_down)     [50000,256] x [256,64]
__global__ __launch_bounds__(256)
void gemm1_kernel(const float* __restrict__ h, const float* __restrict__ W_down) {
    wgemm_core<true, false>(h, W_down, g_xb, NATOMS, NPAD, PIN, PIN, EMB, nullptr);
}

// GEMM2: g_h2 = (g_xba2 @ W_bilinear) * scale   [NPAD,1024] x [1024,64]
__global__ __launch_bounds__(256)
void gemm2_kernel(const float* __restrict__ W_bil, const float* __restrict__ scale) {
    wgemm_core<false, true>(g_xba2, W_bil, g_h2, NPAD, NPAD, POUT, POUT, NRBF * PIN, scale);
}

// GEMM3: out = silu(g_h2 @ W_up)     [NPAD,64] x [64,256]
__global__ __launch_bounds__(256)
void gemm3_kernel(const float* __restrict__ W_up, float* __restrict__ out) {
    wgemm_core<true, false>(g_h2, W_up, out, NPAD, NATOMS, EMB, EMB, POUT, nullptr);
}

// ---------------------------------------------------------------------------
// Fused gather + rbf einsum via tf32 wmma: one warp per atom.
// Per atom: rb[16,32] @ xs[32,64] -> x_ba2[16,64]  (16 m16n16k8 MMAs)
// ---------------------------------------------------------------------------
__global__ __launch_bounds__(128)
void einsum_kernel(const float* __restrict__ rad, const int* __restrict__ ei, int es)
{
    constexpr int LDX = PIN + 4;   // 68
    const int warp = threadIdx.x >> 5;
    const int lane = threadIdx.x & 31;
    const int atom = blockIdx.x * 4 + warp;   // grid = 12500, exact

    __shared__ __align__(16) float xs_all[4][KMAXN * LDX];      // 4 x 8.7 KB
    __shared__ __align__(16) float rbs_all[4][NRBF * KMAXN];    // 4 x 2 KB
    __shared__ int srcs_all[4][KMAXN];

    float* xs   = xs_all[warp];
    float* rbs  = rbs_all[warp];
    int*   srcs = srcs_all[warp];

    // winning source atom per neighbor slot
    {
        int e = g_win[atom * KMAXN + lane];
        int src = -1;
        if (e >= 0) {
            src = ei[(size_t)e * es];   // edge_index[0][e]
            if ((unsigned)src >= NATOMS) src = -1;
        }
        srcs[lane] = src;
    }
    __syncwarp();

    // stage rad_basis[atom]: 512 floats = 128 float4 (tf32-rounded)
    {
        const float4* rg = reinterpret_cast<const float4*>(rad + (size_t)atom * NRBF * KMAXN);
        float4* rs4 = reinterpret_cast<float4*>(rbs);
#pragma unroll
        for (int i = 0; i < 4; i++) {
            float4 v = rg[lane + 32 * i];
            v.x = wmma::__float_to_tf32(v.x);
            v.y = wmma::__float_to_tf32(v.y);
            v.z = wmma::__float_to_tf32(v.z);
            v.w = wmma::__float_to_tf32(v.w);
            rs4[lane + 32 * i] = v;
        }
    }

    // gather x rows: 2 slots per pass, float4 per 16 lanes (L2-resident table)
#pragma unroll
    for (int kk = 0; kk < KMAXN; kk += 2) {
        int k = kk + (lane >> 4);
        int f = lane & 15;
        int src = srcs[k];
        float4 v = make_float4(0.f, 0.f, 0.f, 0.f);
        if (src >= 0) {
            v = reinterpret_cast<const float4*>(g_xb + (size_t)src * PIN)[f];
            v.x = wmma::__float_to_tf32(v.x);
            v.y = wmma::__float_to_tf32(v.y);
            v.z = wmma::__float_to_tf32(v.z);
            v.w = wmma::__float_to_tf32(v.w);
        }
        *reinterpret_cast<float4*>(xs + k * LDX + f * 4) = v;
    }
    __syncwarp();

    // 16 MMAs: c[n] (16x16) over 4 k-steps
    wmma::fragment<wmma::accumulator, 16, 16, 8, float> c[4];
#pragma unroll
    for (int n = 0; n < 4; n++) wmma::fill_fragment(c[n], 0.0f);

#pragma unroll
    for (int k = 0; k < 4; k++) {
        wmma::fragment<wmma::matrix_a, 16, 16, 8, wmma::precision::tf32, wmma::row_major> a;
        wmma::load_matrix_sync(a, rbs + k * 8, KMAXN);
#pragma unroll
        for (int n = 0; n < 4; n++) {
            wmma::fragment<wmma::matrix_b, 16, 16, 8, wmma::precision::tf32, wmma::row_major> b;
            wmma::load_matrix_sync(b, xs + (k * 8) * LDX + n * 16, LDX);
            wmma::mma_sync(c[n], a, b, c[n]);
        }
    }

    // write x_ba2[atom] : [16,64] row-major (flat r*64+d matches W_bilinear rows)
    float* outp = g_xba2 + (size_t)atom * NRBF * PIN;
#pragma unroll
    for (int n = 0; n < 4; n++)
        wmma::store_matrix_sync(outp + n * 16, c[n], PIN, wmma::mem_row_major);
}

// ---------------------------------------------------------------------------
// Launch — kernel launches ONLY (graph-capturable)
// ---------------------------------------------------------------------------
extern "C" void kernel_launch(void* const* d_in, const int* in_sizes, int n_in,
                              void* d_out, int out_size)
{
    const float* h         = (const float*)d_in[0];   // [50000,256]
    const float* rad_basis = (const float*)d_in[1];   // [50000,16,32]
    const int*   edge_idx  = (const int*)d_in[2];     // [2,1.6M] int32 OR int64
    const int*   tni       = (const int*)d_in[3];     // [1.6M]   int32 OR int64
    const float* W_down    = (const float*)d_in[4];   // [256,64]
    const float* W_bil     = (const float*)d_in[5];   // [1024,64]
    const float* W_up      = (const float*)d_in[6];   // [64,256]
    const float* scale     = (const float*)d_in[7];   // [1]
    float* out = (float*)d_out;                       // [50000,256]

    // Word stride per logical index element (int32 vs int64-as-pairs)
    int es = (in_sizes[2] >= 2 * NEDGES * 2) ? 2 : 1;
    int ts = (in_sizes[3] >= NEDGES * 2) ? 2 : 1;

    init_win_kernel<<<(NATOMS * KMAXN + 255) / 256, 256>>>();
    scatter_win_kernel<<<(NEDGES + 255) / 256, 256>>>(edge_idx, tni, es, ts);

    { dim3 grid(1, NPAD / 128);
      gemm1_kernel<<<grid, 256>>>(h, W_down); }

    einsum_kernel<<<NATOMS / 4, 128>>>(rad_basis, edge_idx, es);

    { dim3 grid(1, NPAD / 128);
      gemm2_kernel<<<grid, 256>>>(W_bil, scale); }

    { dim3 grid(EMB / 64, NPAD / 128);
      gemm3_kernel<<<grid, 256>>>(W_up, out); }
}